// round 1
// baseline (speedup 1.0000x reference)
#include <cuda_runtime.h>
#include <cstdint>

// Problem constants: B=8, C=256, H=W=64, K=3, pad=1, stride=1
// L = 64*64 = 4096, k*k = 9, per-(b,c) output floats = 9*L = 36864
#define HW      64
#define LSZ     4096
#define FPC     36864          // floats per (b,c) slice of output
#define F4PC    (FPC / 4)      // 9216 float4 groups per (b,c)

// Zero-padded unfold read: patch offset kk in [0,9), location l in [0,4096)
__device__ __forceinline__ float patch_val(const float* __restrict__ base,
                                           int kk, int l) {
    int row = (l >> 6) + (kk / 3) - 1;
    int col = (l & 63) + (kk % 3) - 1;
    bool ok = ((unsigned)row < (unsigned)HW) & ((unsigned)col < (unsigned)HW);
    return ok ? __ldg(base + row * HW + col) : 0.0f;
}

__global__ void __launch_bounds__(256)
appearance_kernel(const float* __restrict__ key,
                  const float* __restrict__ query,
                  float* __restrict__ out) {
    const int bc = blockIdx.y;                              // (b*C + c), 0..2047
    const int f4 = blockIdx.x * blockDim.x + threadIdx.x;   // 0..9215
    const int f  = f4 << 2;                                 // flat idx within slice

    const float* kb = key   + (size_t)bc * LSZ;
    const float* qb = query + (size_t)bc * LSZ;

    // ---- key factor: kk constant across the 4 (f aligned to 4, L%4==0) ----
    const int kk  = f >> 12;            // 0..8
    const int l   = f & 4095;
    const int row = l >> 6;
    const int col = l & 63;             // multiple of 4, so col <= 60: single row
    const int r   = row + (kk / 3) - 1;
    const int cb  = col + (kk % 3) - 1; // column of j=0
    const bool rok = (unsigned)r < (unsigned)HW;
    const float* kp = kb + r * HW + cb;

    const float k0 = (rok && cb >= 0)      ? __ldg(kp + 0) : 0.0f;
    const float k1 =  rok                  ? __ldg(kp + 1) : 0.0f; // cb+1 in [0,62]
    const float k2 =  rok                  ? __ldg(kp + 2) : 0.0f; // cb+2 in [1,63]
    const float k3 = (rok && cb + 3 < HW)  ? __ldg(kp + 3) : 0.0f;

    // ---- query factor: l' = (f+j)/9; at most 2 distinct values in the group ----
    const int lp0 = f / 9;              // constant div -> mul-hi
    const int rem = f - lp0 * 9;        // 0..8
    const int fq0 = lp0 * 9 + 4;
    const float q0 = patch_val(qb, fq0 >> 12, fq0 & 4095);
    float q1 = q0;
    if (rem >= 6) {                     // group crosses into l'+1
        const int fq1 = fq0 + 9;        // (lp0+1)*9+4, lp0+1 <= 4095 guaranteed
        q1 = patch_val(qb, fq1 >> 12, fq1 & 4095);
    }
    const int cross = 9 - rem;          // j >= cross uses q1 (cross >= 1)

    float4 o;
    o.x = k0 * q0;                       // j=0: always q0 (cross >= 1)
    o.y = k1 * ((1 >= cross) ? q1 : q0);
    o.z = k2 * ((2 >= cross) ? q1 : q0);
    o.w = k3 * ((3 >= cross) ? q1 : q0);

    reinterpret_cast<float4*>(out + (size_t)bc * FPC)[f4] = o;
}

extern "C" void kernel_launch(void* const* d_in, const int* in_sizes, int n_in,
                              void* d_out, int out_size) {
    const float* key   = (const float*)d_in[0];
    const float* query = (const float*)d_in[1];
    float* out = (float*)d_out;

    // grid.x sweeps one (b,c) slice (keeps 32KB working set L1/L2-hot),
    // grid.y = B*C = 2048 slices.
    dim3 grid(F4PC / 256, 2048);   // (36, 2048)
    appearance_kernel<<<grid, 256>>>(key, query, out);
}

// round 2
// speedup vs baseline: 1.7125x; 1.7125x over previous
#include <cuda_runtime.h>
#include <cstdint>

// Problem: B=8, C=256, H=W=64, K=3, pad=1, stride=1
// L = 4096, k*k = 9, per-(b,c) output floats = 9*L = 36864 (= 9216 float4)
// out_flat[f] = keyflat[f] * qv[f/9], where
//   keyflat[f]  = patch(key,  f>>12, f&4095)
//   qv[l']      = patch(query, (9l'+4)>>12, (9l'+4)&4095)
#define HW    64
#define PITCH 66           // padded tile pitch (64 + 2 halo)
#define LSZ   4096
#define F4PC  9216         // float4 groups per (b,c) slice

__global__ void __launch_bounds__(256)
appearance_kernel(const float* __restrict__ key,
                  const float* __restrict__ query,
                  float* __restrict__ out) {
    __shared__ float pad[PITCH * PITCH];  // 17424 B, reused: query then key
    __shared__ float qv[LSZ + 1];         // 16388 B

    const int tid = threadIdx.x;
    const int bc  = blockIdx.x;           // 0..2047

    const float4* kb4 = (const float4*)(key   + (size_t)bc * LSZ);
    const float4* qb4 = (const float4*)(query + (size_t)bc * LSZ);

    // ---- zero the padded tile (borders must be 0) ----
    #pragma unroll
    for (int i = tid; i < PITCH * PITCH; i += 256) pad[i] = 0.0f;
    __syncthreads();

    // ---- phase 1: query -> padded tile ----
    #pragma unroll
    for (int i = tid; i < LSZ / 4; i += 256) {
        float4 v = qb4[i];
        int l = i << 2;
        float* p = &pad[((l >> 6) + 1) * PITCH + (l & 63) + 1];
        p[0] = v.x; p[1] = v.y; p[2] = v.z; p[3] = v.w;
    }
    __syncthreads();

    // ---- qv[l'] = query patch at fq = 9*l' + 4 (no bounds checks) ----
    #pragma unroll
    for (int i = tid; i < LSZ; i += 256) {
        int fq = 9 * i + 4;
        int kk = fq >> 12;
        int lq = fq & 4095;
        qv[i] = pad[((lq >> 6) + kk / 3) * PITCH + (lq & 63) + kk % 3];
    }
    if (tid == 0) qv[LSZ] = 0.0f;
    __syncthreads();

    // ---- phase 2: key -> padded tile (borders already zero) ----
    #pragma unroll
    for (int i = tid; i < LSZ / 4; i += 256) {
        float4 v = kb4[i];
        int l = i << 2;
        float* p = &pad[((l >> 6) + 1) * PITCH + (l & 63) + 1];
        p[0] = v.x; p[1] = v.y; p[2] = v.z; p[3] = v.w;
    }
    __syncthreads();

    // ---- main loop: 36 float4 outputs per thread ----
    float4* out4 = (float4*)out + (size_t)bc * F4PC;
    const int l0  = tid << 2;                 // base l for it=0 (multiple of 4)
    const int row = l0 >> 6;
    const int col = l0 & 63;

    #pragma unroll
    for (int kk = 0; kk < 9; kk++) {
        const int dr = kk / 3, dc = kk % 3;
        #pragma unroll
        for (int it = 0; it < 4; it++) {
            // l = it*1024 + tid*4  ->  row increases by 16 per it, col fixed
            const float* kp = &pad[(row + it * 16 + dr) * PITCH + col + dc];
            const float k0 = kp[0], k1 = kp[1], k2 = kp[2], k3 = kp[3];

            const int f   = kk * LSZ + it * 1024 + l0;
            const unsigned lp0 = (unsigned)f / 9u;   // mul-hi
            const int rem = f - (int)lp0 * 9;        // 0..8
            const float q0 = qv[lp0];
            const float q1 = qv[lp0 + 1];

            float4 o;
            o.x = k0 * q0;                           // j=0 always uses q0
            o.y = k1 * (rem >= 8 ? q1 : q0);
            o.z = k2 * (rem >= 7 ? q1 : q0);
            o.w = k3 * (rem >= 6 ? q1 : q0);
            out4[kk * 1024 + it * 256 + tid] = o;
        }
    }
}

extern "C" void kernel_launch(void* const* d_in, const int* in_sizes, int n_in,
                              void* d_out, int out_size) {
    const float* key   = (const float*)d_in[0];
    const float* query = (const float*)d_in[1];
    float* out = (float*)d_out;

    appearance_kernel<<<2048, 256>>>(key, query, out);
}